// round 3
// baseline (speedup 1.0000x reference)
#include <cuda_runtime.h>
#include <cstdint>

// Problem constants
static constexpr int Lc  = 32;
static constexpr int Kc  = 4;
static constexpr int Dc  = 1024;
static constexpr int QOc = 1024;
static constexpr int KVc = 256;
static constexpr int FFc = 2816;

static constexpr int S = 256;   // stage width (floats per cursed vec)

typedef unsigned long long ull;

// ---------------- f32x2 packed FMA (sm_103a FFMA2) ----------------
__device__ __forceinline__ void ffma2(ull& acc, ull a, ull b) {
    asm("fma.rn.f32x2 %0, %1, %2, %0;" : "+l"(acc) : "l"(a), "l"(b));
}
__device__ __forceinline__ float f32x2_hsum(ull v) {
    return __uint_as_float((uint32_t)v) + __uint_as_float((uint32_t)(v >> 32));
}

// ---------------- cp.async helpers ----------------
__device__ __forceinline__ void cp_async16(uint32_t saddr, const void* gptr) {
    asm volatile("cp.async.cg.shared.global [%0], [%1], 16;" :: "r"(saddr), "l"(gptr));
}
__device__ __forceinline__ void cp_commit() {
    asm volatile("cp.async.commit_group;");
}
template<int N>
__device__ __forceinline__ void cp_wait() {
    asm volatile("cp.async.wait_group %0;" :: "n"(N));
}

// Stage M x S floats of cursed data (cols [c0,c0+S)) into one smem slot. 128 thr.
template<int M, int I>
__device__ __forceinline__ void stage_cursed(uint32_t sbuf, const float* __restrict__ Cl,
                                             int c0, int tid)
{
#pragma unroll
    for (int idx = tid; idx < M * (S / 4); idx += 128) {
        const int j   = idx >> 6;        // S/4 = 64
        const int col = idx & 63;
        cp_async16(sbuf + (uint32_t)(j * S + col * 4) * 4u,
                   Cl + (size_t)j * I + c0 + col * 4);
    }
}

// ---------------- projection tile ----------------
// Block: 128 threads = 4 warps; each warp owns 4 d-rows; block owns 16 rows.
template<int M, int I, bool IS_MLP, int MFIX>
__device__ __forceinline__ void proj_tile(
    const float* __restrict__ Wl,   // layer weight [D][I]
    const float* __restrict__ Cl,   // layer cursed vecs [M][I]
    float* __restrict__ out,
    float* __restrict__ smem,       // [3][M*S]
    int l, int d0)
{
    const int tid   = threadIdx.x;
    const int lane  = tid & 31;
    const int warp  = tid >> 5;
    const int dbase = d0 + warp * 4;
    const uint32_t smem_u32 = (uint32_t)__cvta_generic_to_shared(smem);
    constexpr int NS = I / S;
    constexpr uint32_t SLOT = (uint32_t)(M * S * 4);   // bytes per ring slot

    ull acc2[4][M];
#pragma unroll
    for (int t = 0; t < 4; ++t)
#pragma unroll
        for (int j = 0; j < M; ++j) acc2[t][j] = 0ull;

    const float* wrow = Wl + (size_t)dbase * I;

    // Prime 3-slot ring
    stage_cursed<M, I>(smem_u32, Cl, 0, tid);
    cp_commit();
    if (NS > 1) {
        stage_cursed<M, I>(smem_u32 + SLOT, Cl, S, tid);
        cp_commit();
    }

    for (int s = 0; s < NS; ++s) {
        const int c0 = s * S;
        if (s < NS - 1) cp_wait<1>(); else cp_wait<0>();
        __syncthreads();

        const float* cbuf = smem + (s % 3) * (M * S);

#pragma unroll
        for (int u = 0; u < 2; ++u) {
            // 4 weight rows, 16B each, loaded as double2 (f32x2 pairs, L2-only)
            ull w01[4], w23[4];
#pragma unroll
            for (int t = 0; t < 4; ++t) {
                const double2 wd = __ldcg(reinterpret_cast<const double2*>(
                    wrow + (size_t)t * I + c0 + u * 128 + lane * 4));
                w01[t] = __double_as_longlong(wd.x);
                w23[t] = __double_as_longlong(wd.y);
            }
#pragma unroll
            for (int j = 0; j < M; ++j) {
                const double2 cd = *reinterpret_cast<const double2*>(
                    cbuf + j * S + u * 128 + lane * 4);
                const ull c01 = __double_as_longlong(cd.x);
                const ull c23 = __double_as_longlong(cd.y);
#pragma unroll
                for (int t = 0; t < 4; ++t) {
                    ffma2(acc2[t][j], w01[t], c01);
                    ffma2(acc2[t][j], w23[t], c23);
                }
            }
        }

        if (s + 2 < NS) {
            stage_cursed<M, I>(smem_u32 + (uint32_t)((s + 2) % 3) * SLOT,
                               Cl, c0 + 2 * S, tid);
            cp_commit();
        }
    }

    // Horizontal sum of each f32x2 pair, then butterfly across lanes.
    float acc[4][M];
#pragma unroll
    for (int j = 0; j < M; ++j)
#pragma unroll
        for (int t = 0; t < 4; ++t) {
            float v = f32x2_hsum(acc2[t][j]);
            v += __shfl_xor_sync(0xffffffffu, v, 16);
            v += __shfl_xor_sync(0xffffffffu, v, 8);
            v += __shfl_xor_sync(0xffffffffu, v, 4);
            v += __shfl_xor_sync(0xffffffffu, v, 2);
            v += __shfl_xor_sync(0xffffffffu, v, 1);
            acc[t][j] = v;
        }

    // Scatter stores (lane ((j*4+t)&31) writes result (j,t))
#pragma unroll
    for (int j = 0; j < M; ++j) {
        int m, k;
        if (IS_MLP) {
            const int mi = j >> 2;            // 0,1,2 -> gate, up, down
            m = (mi == 2) ? 6 : (3 + mi);     // gate=3, up=4, down=6
            k = j & 3;
        } else {
            m = MFIX;
            k = j;
        }
        const size_t row = ((size_t)(l * 7 + m) * 2 + 1) * Kc + k;
#pragma unroll
        for (int t = 0; t < 4; ++t) {
            if (lane == ((j * 4 + t) & 31))
                out[row * Dc + (size_t)(dbase + t)] = acc[t][j];
        }
    }
}

// Block segments (16 d-rows per proj block):
//   [0,2048)      mlp   [2048,4096)  q   [4096,6144)  o
//   [6144,8192)   k     [8192,10240) v   [10240,10496) residual copy
extern "C" __global__ void __launch_bounds__(128, 3)
both_sides_fused(const float* __restrict__ residual,
                 const float* __restrict__ cq, const float* __restrict__ ck,
                 const float* __restrict__ cv, const float* __restrict__ co,
                 const float* __restrict__ cm,
                 const float* __restrict__ Wq, const float* __restrict__ Wk,
                 const float* __restrict__ Wv, const float* __restrict__ Wo,
                 const float* __restrict__ Wd,
                 float* __restrict__ out)
{
    __shared__ __align__(16) float smem[3][12 * S];   // 36 KB

    int b = blockIdx.x;
    if (b < 2048) {                                   // mlp (heaviest first)
        const int l = b >> 6, d0 = (b & 63) * 16;
        proj_tile<12, FFc, true, 0>(Wd + (size_t)l * Dc * FFc,
                                    cm + (size_t)l * 3 * Kc * FFc,
                                    out, &smem[0][0], l, d0);
    } else if (b < 4096) {                            // q (m=0)
        b -= 2048;
        const int l = b >> 6, d0 = (b & 63) * 16;
        proj_tile<4, QOc, false, 0>(Wq + (size_t)l * Dc * QOc,
                                    cq + (size_t)l * Kc * QOc,
                                    out, &smem[0][0], l, d0);
    } else if (b < 6144) {                            // o (m=5)
        b -= 4096;
        const int l = b >> 6, d0 = (b & 63) * 16;
        proj_tile<4, QOc, false, 5>(Wo + (size_t)l * Dc * QOc,
                                    co + (size_t)l * Kc * QOc,
                                    out, &smem[0][0], l, d0);
    } else if (b < 8192) {                            // k (m=1)
        b -= 6144;
        const int l = b >> 6, d0 = (b & 63) * 16;
        proj_tile<4, KVc, false, 1>(Wk + (size_t)l * Dc * KVc,
                                    ck + (size_t)l * Kc * KVc,
                                    out, &smem[0][0], l, d0);
    } else if (b < 10240) {                           // v (m=2)
        b -= 8192;
        const int l = b >> 6, d0 = (b & 63) * 16;
        proj_tile<4, KVc, false, 2>(Wv + (size_t)l * Dc * KVc,
                                    cv + (size_t)l * Kc * KVc,
                                    out, &smem[0][0], l, d0);
    } else {                                          // residual copy (s=0 rows)
        const float4* r4 = reinterpret_cast<const float4*>(residual);
        float4* o4 = reinterpret_cast<float4*>(out);
        const int nf4 = Lc * 7 * Kc * Dc / 4;         // 229376 float4
        for (int i = (b - 10240) * 128 + (int)threadIdx.x; i < nf4; i += 256 * 128) {
            const int chunk  = i >> 10;
            const int within = i & 1023;
            o4[(size_t)chunk * 2048 + within] = r4[i];
        }
    }
}

extern "C" void kernel_launch(void* const* d_in, const int* in_sizes, int n_in,
                              void* d_out, int out_size)
{
    const float* residual = (const float*)d_in[0];
    const float* cq       = (const float*)d_in[1];
    const float* ck       = (const float*)d_in[2];
    const float* cv       = (const float*)d_in[3];
    const float* co       = (const float*)d_in[4];
    const float* cm       = (const float*)d_in[5];
    const float* Wq       = (const float*)d_in[6];
    const float* Wk       = (const float*)d_in[7];
    const float* Wv       = (const float*)d_in[8];
    const float* Wo       = (const float*)d_in[9];
    const float* Wd       = (const float*)d_in[10];
    float* out            = (float*)d_out;

    both_sides_fused<<<10496, 128>>>(residual, cq, ck, cv, co, cm,
                                     Wq, Wk, Wv, Wo, Wd, out);
}

// round 4
// speedup vs baseline: 1.0491x; 1.0491x over previous
#include <cuda_runtime.h>
#include <cstdint>

// Problem constants
static constexpr int Lc  = 32;
static constexpr int Kc  = 4;
static constexpr int Dc  = 1024;
static constexpr int QOc = 1024;
static constexpr int KVc = 256;
static constexpr int FFc = 2816;

static constexpr int S        = 256;              // stage width (floats)
static constexpr int ROWS_BLK = 16;               // d-rows per block
static constexpr int RW       = 8;                // rows per warp (row-group)
static constexpr int WSLOT_F  = ROWS_BLK * S;     // 4096 floats = 16 KB weights
static constexpr int CSLOT_F  = 12 * S;           // 3072 floats = 12 KB cursed (max M)
static constexpr int SLOT_F   = WSLOT_F + CSLOT_F;// 7168 floats = 28 KB / slot
static constexpr int NSLOT    = 3;
static constexpr int SMEM_BYTES = NSLOT * SLOT_F * 4;   // 84 KB

typedef unsigned long long ull;

// ---------------- f32x2 packed FMA ----------------
__device__ __forceinline__ void ffma2(ull& acc, ull a, ull b) {
    asm("fma.rn.f32x2 %0, %1, %2, %0;" : "+l"(acc) : "l"(a), "l"(b));
}
__device__ __forceinline__ float hsum2(ull v) {
    return __uint_as_float((uint32_t)v) + __uint_as_float((uint32_t)(v >> 32));
}

// ---------------- cp.async helpers ----------------
__device__ __forceinline__ void cp_async16(uint32_t saddr, const void* gptr) {
    asm volatile("cp.async.cg.shared.global [%0], [%1], 16;" :: "r"(saddr), "l"(gptr));
}
__device__ __forceinline__ void cp_commit() {
    asm volatile("cp.async.commit_group;");
}
template<int N>
__device__ __forceinline__ void cp_wait() {
    asm volatile("cp.async.wait_group %0;" :: "n"(N));
}

// Stage (weights 16 rows x S) + (cursed M x S) for columns [c0, c0+S).
// 256 threads. Weight row r of this block is global row (block base + r).
template<int M, int I>
__device__ __forceinline__ void stage_all(uint32_t slot,
                                          const float* __restrict__ Wrows, // Wl + dblk*I
                                          const float* __restrict__ Cl,
                                          int c0, int tid)
{
    constexpr int NW = ROWS_BLK * (S / 4);          // 1024 weight 16B-transfers
    constexpr int NC = M * (S / 4);                 // cursed transfers
#pragma unroll
    for (int idx = tid; idx < NW + NC; idx += 256) {
        if (idx < NW) {
            const int r   = idx >> 6;               // S/4 = 64 per row
            const int c16 = idx & 63;
            cp_async16(slot + (uint32_t)(r * S + c16 * 4) * 4u,
                       Wrows + (size_t)r * I + c0 + c16 * 4);
        } else {
            const int j   = (idx - NW) >> 6;
            const int c16 = (idx - NW) & 63;
            cp_async16(slot + (uint32_t)(WSLOT_F + j * S + c16 * 4) * 4u,
                       Cl + (size_t)j * I + c0 + c16 * 4);
        }
    }
}

// ---------------- projection tile ----------------
// Block: 256 threads = 8 warps = 2 row-groups(8 rows) x 4 M-groups(MG vecs).
// Block owns 16 d-rows, all M vecs.
template<int M, int MG, int I, bool IS_MLP, int MFIX>
__device__ __forceinline__ void proj_tile(
    const float* __restrict__ Wl,   // layer weight [D][I]
    const float* __restrict__ Cl,   // layer cursed vecs [M][I]
    float* __restrict__ out,
    float* __restrict__ smem,       // dynamic, [NSLOT][SLOT_F]
    int l, int d0)
{
    const int tid   = threadIdx.x;
    const int lane  = tid & 31;
    const int warp  = tid >> 5;
    const int rg    = warp >> 2;          // row-group 0/1
    const int g     = warp & 3;           // M-group 0..3
    const int dbase = d0 + rg * RW;
    const uint32_t smem_u32 = (uint32_t)__cvta_generic_to_shared(smem);
    constexpr int NS = I / S;
    constexpr uint32_t SLOTB = (uint32_t)(SLOT_F * 4);

    ull acc2[RW][MG];
#pragma unroll
    for (int t = 0; t < RW; ++t)
#pragma unroll
        for (int j = 0; j < MG; ++j) acc2[t][j] = 0ull;

    const float* Wrows = Wl + (size_t)d0 * I;   // block's 16 rows

    // Prime ring (up to 2 slots)
    stage_all<M, I>(smem_u32, Wrows, Cl, 0, tid);
    cp_commit();
    if (NS > 1) {
        stage_all<M, I>(smem_u32 + SLOTB, Wrows, Cl, S, tid);
        cp_commit();
    }

    for (int s = 0; s < NS; ++s) {
        if (s == NS - 1) cp_wait<0>(); else cp_wait<1>();
        __syncthreads();

        const float* slot = smem + (s % 3) * SLOT_F;
        const float* wbuf = slot;
        const float* cbuf = slot + WSLOT_F;

#pragma unroll
        for (int u = 0; u < 2; ++u) {
            ull c01[MG], c23[MG];
#pragma unroll
            for (int j = 0; j < MG; ++j) {
                const double2 cd = *reinterpret_cast<const double2*>(
                    cbuf + (g * MG + j) * S + u * 128 + lane * 4);
                c01[j] = __double_as_longlong(cd.x);
                c23[j] = __double_as_longlong(cd.y);
            }
#pragma unroll
            for (int t = 0; t < RW; ++t) {
                const double2 wd = *reinterpret_cast<const double2*>(
                    wbuf + (rg * RW + t) * S + u * 128 + lane * 4);
                const ull w01 = __double_as_longlong(wd.x);
                const ull w23 = __double_as_longlong(wd.y);
#pragma unroll
                for (int j = 0; j < MG; ++j) {
                    ffma2(acc2[t][j], w01, c01[j]);
                    ffma2(acc2[t][j], w23, c23[j]);
                }
            }
        }

        // Prefetch stage s+2 into slot (s+2)%3 (stage s-1's slot; this CTA
        // passed the barrier above, so s-1 compute is done -> safe).
        if (s + 2 < NS) {
            stage_all<M, I>(smem_u32 + (uint32_t)((s + 2) % 3) * SLOTB,
                            Wrows, Cl, (s + 2) * S, tid);
            cp_commit();
        }
    }

    // Reduce: fold f32x2 pairs, butterfly across lanes, scatter stores.
#pragma unroll
    for (int t = 0; t < RW; ++t)
#pragma unroll
        for (int j = 0; j < MG; ++j) {
            float v = hsum2(acc2[t][j]);
            v += __shfl_xor_sync(0xffffffffu, v, 16);
            v += __shfl_xor_sync(0xffffffffu, v, 8);
            v += __shfl_xor_sync(0xffffffffu, v, 4);
            v += __shfl_xor_sync(0xffffffffu, v, 2);
            v += __shfl_xor_sync(0xffffffffu, v, 1);
            if (lane == t * MG + j) {
                const int jj = g * MG + j;          // global vec index
                int m, k;
                if (IS_MLP) {
                    const int mi = jj >> 2;          // 0,1,2 -> gate, up, down
                    m = (mi == 2) ? 6 : (3 + mi);    // gate=3, up=4, down=6
                    k = jj & 3;
                } else {
                    m = MFIX;
                    k = jj;
                }
                const size_t row = ((size_t)(l * 7 + m) * 2 + 1) * Kc + k;
                out[row * Dc + (size_t)(dbase + t)] = v;
            }
        }
}

// Block segments (16 d-rows per proj block, 2048 blocks per matrix):
//   [0,2048) mlp  [2048,4096) q  [4096,6144) o  [6144,8192) k
//   [8192,10240) v  [10240,10496) residual copy
extern "C" __global__ void __launch_bounds__(256, 2)
both_sides_fused(const float* __restrict__ residual,
                 const float* __restrict__ cq, const float* __restrict__ ck,
                 const float* __restrict__ cv, const float* __restrict__ co,
                 const float* __restrict__ cm,
                 const float* __restrict__ Wq, const float* __restrict__ Wk,
                 const float* __restrict__ Wv, const float* __restrict__ Wo,
                 const float* __restrict__ Wd,
                 float* __restrict__ out)
{
    extern __shared__ __align__(16) float smem[];

    int b = blockIdx.x;
    if (b < 2048) {                                   // mlp (heaviest first)
        const int l = b >> 6, d0 = (b & 63) * ROWS_BLK;
        proj_tile<12, 3, FFc, true, 0>(Wd + (size_t)l * Dc * FFc,
                                       cm + (size_t)l * 3 * Kc * FFc,
                                       out, smem, l, d0);
    } else if (b < 4096) {                            // q (m=0)
        b -= 2048;
        const int l = b >> 6, d0 = (b & 63) * ROWS_BLK;
        proj_tile<4, 1, QOc, false, 0>(Wq + (size_t)l * Dc * QOc,
                                       cq + (size_t)l * Kc * QOc,
                                       out, smem, l, d0);
    } else if (b < 6144) {                            // o (m=5)
        b -= 4096;
        const int l = b >> 6, d0 = (b & 63) * ROWS_BLK;
        proj_tile<4, 1, QOc, false, 5>(Wo + (size_t)l * Dc * QOc,
                                       co + (size_t)l * Kc * QOc,
                                       out, smem, l, d0);
    } else if (b < 8192) {                            // k (m=1)
        b -= 6144;
        const int l = b >> 6, d0 = (b & 63) * ROWS_BLK;
        proj_tile<4, 1, KVc, false, 1>(Wk + (size_t)l * Dc * KVc,
                                       ck + (size_t)l * Kc * KVc,
                                       out, smem, l, d0);
    } else if (b < 10240) {                           // v (m=2)
        b -= 8192;
        const int l = b >> 6, d0 = (b & 63) * ROWS_BLK;
        proj_tile<4, 1, KVc, false, 2>(Wv + (size_t)l * Dc * KVc,
                                       cv + (size_t)l * Kc * KVc,
                                       out, smem, l, d0);
    } else {                                          // residual copy (s=0 rows)
        const float4* r4 = reinterpret_cast<const float4*>(residual);
        float4* o4 = reinterpret_cast<float4*>(out);
        const int nf4 = Lc * 7 * Kc * Dc / 4;         // 229376 float4
        for (int i = (b - 10240) * 256 + (int)threadIdx.x; i < nf4; i += 256 * 256) {
            const int chunk  = i >> 10;
            const int within = i & 1023;
            o4[(size_t)chunk * 2048 + within] = r4[i];
        }
    }
}

extern "C" void kernel_launch(void* const* d_in, const int* in_sizes, int n_in,
                              void* d_out, int out_size)
{
    const float* residual = (const float*)d_in[0];
    const float* cq       = (const float*)d_in[1];
    const float* ck       = (const float*)d_in[2];
    const float* cv       = (const float*)d_in[3];
    const float* co       = (const float*)d_in[4];
    const float* cm       = (const float*)d_in[5];
    const float* Wq       = (const float*)d_in[6];
    const float* Wk       = (const float*)d_in[7];
    const float* Wv       = (const float*)d_in[8];
    const float* Wo       = (const float*)d_in[9];
    const float* Wd       = (const float*)d_in[10];
    float* out            = (float*)d_out;

    static bool attr_set = false;
    if (!attr_set) {
        cudaFuncSetAttribute(both_sides_fused,
                             cudaFuncAttributeMaxDynamicSharedMemorySize,
                             SMEM_BYTES);
        attr_set = true;
    }

    both_sides_fused<<<10496, 256, SMEM_BYTES>>>(residual, cq, ck, cv, co, cm,
                                                 Wq, Wk, Wv, Wo, Wd, out);
}